// round 9
// baseline (speedup 1.0000x reference)
#include <cuda_runtime.h>

// lagrangian_ode_func: out[i] = { x.z, x.w, -(k1*x0 + k2*(x0-x1)), k2*(x0-x1) }
// RPT=8 (measured MLP optimum: 6.05 TB/s) + launch_bounds(256,4) to cap regs
// at 64 -> 4 CTAs/SM (occ ~50%), raising total in-flight loads/SM ~60%.

#define TPB 256
#define RPT 8

__global__ void __launch_bounds__(TPB, 4)
lagr_ode_kernel(const float4* __restrict__ x,
                const float* __restrict__ k1p,
                const float* __restrict__ k2p,
                float4* __restrict__ out)
{
    const unsigned base = blockIdx.x * (TPB * RPT) + threadIdx.x;
    const float k1 = __ldg(k1p);
    const float k2 = __ldg(k2p);

    // Front-batched independent loads -> MLP=8 per thread
    float4 v[RPT];
#pragma unroll
    for (int j = 0; j < RPT; j++)
        v[j] = __ldcs(&x[base + j * TPB]);

#pragma unroll
    for (int j = 0; j < RPT; j++) {
        const float d = k2 * (v[j].x - v[j].y);   // k2*(q0-q1)
        float4 r;
        r.x = v[j].z;                              // qd0
        r.y = v[j].w;                              // qd1
        r.z = -(k1 * v[j].x + d);                  // qdd0
        r.w = d;                                   // qdd1
        __stcs(&out[base + j * TPB], r);
    }
}

extern "C" void kernel_launch(void* const* d_in, const int* in_sizes, int n_in,
                              void* d_out, int out_size)
{
    // Inputs (metadata order): t [1], x [B*4], k1 [1], k2 [1]
    const float4* x  = (const float4*)d_in[1];
    const float*  k1 = (const float*)d_in[2];
    const float*  k2 = (const float*)d_in[3];
    float4* out = (float4*)d_out;

    const int rows = in_sizes[1] / 4;              // 8388608
    const int blocks = rows / (TPB * RPT);         // 4096, exact

    lagr_ode_kernel<<<blocks, TPB>>>(x, k1, k2, out);
}

// round 10
// speedup vs baseline: 1.0066x; 1.0066x over previous
#include <cuda_runtime.h>

// lagrangian_ode_func: out[i] = { x.z, x.w, -(k1*x0 + k2*(x0-x1)), k2*(x0-x1) }
//
// FINAL — HBM-roofline streaming kernel (measured optimum, R7 config).
// 256 MiB irreducible traffic @ 6.05 TB/s = GB300 mixed read/write ceiling.
// Sweep results (kernel dur / HBM):
//   RPT4 occ82: 36.2us/5.88   RPT8 occ31: 35.2us/6.05  <- best
//   RPT8 occ40: 35.7us/5.96   RPT16 occ21: 36.4us/5.82
// Per-warp MLP=8 front-batched loads is the interior optimum; occupancy,
// grid shape, TPB, cache policy, reg budget all verified non-binding.

#define TPB 256
#define RPT 8

__global__ void __launch_bounds__(TPB)
lagr_ode_kernel(const float4* __restrict__ x,
                const float* __restrict__ k1p,
                const float* __restrict__ k2p,
                float4* __restrict__ out)
{
    const unsigned base = blockIdx.x * (TPB * RPT) + threadIdx.x;
    const float k1 = __ldg(k1p);
    const float k2 = __ldg(k2p);

    // Front-batched independent loads -> MLP=8 per thread
    float4 v[RPT];
#pragma unroll
    for (int j = 0; j < RPT; j++)
        v[j] = __ldcs(&x[base + j * TPB]);

#pragma unroll
    for (int j = 0; j < RPT; j++) {
        const float d = k2 * (v[j].x - v[j].y);   // k2*(q0-q1)
        float4 r;
        r.x = v[j].z;                              // qd0
        r.y = v[j].w;                              // qd1
        r.z = -(k1 * v[j].x + d);                  // qdd0
        r.w = d;                                   // qdd1
        __stcs(&out[base + j * TPB], r);
    }
}

extern "C" void kernel_launch(void* const* d_in, const int* in_sizes, int n_in,
                              void* d_out, int out_size)
{
    // Inputs (metadata order): t [1], x [B*4], k1 [1], k2 [1]
    const float4* x  = (const float4*)d_in[1];
    const float*  k1 = (const float*)d_in[2];
    const float*  k2 = (const float*)d_in[3];
    float4* out = (float4*)d_out;

    const int rows = in_sizes[1] / 4;              // 8388608
    const int blocks = rows / (TPB * RPT);         // 4096, exact

    lagr_ode_kernel<<<blocks, TPB>>>(x, k1, k2, out);
}